// round 15
// baseline (speedup 1.0000x reference)
#include <cuda_runtime.h>

// Problem constants (shapes fixed by the dataset)
#define B 16
#define F 256
#define T 8192
#define KKEEP 204                 // k = int(256 * (1 - 0.2))

#define N1 (B * F * T)            // 33,554,432 floats per output tensor
#define N4_MASKED (N1 / 4)        // 8,388,608 float4 (masked_x half)

// R8-proven streamer geometry: 256 threads, ILP 4 -> 1024 f4 per block,
// contiguous [masked | bcast] layout (R12/R13: beats any interleave).
#define BLK_F4 1024
#define MASKED_BLOCKS 8192        // 8192 * 1024 f4 = N4_MASKED
#define BCAST_BLOCKS 8192
#define GRID_TOTAL (MASKED_BLOCKS + BCAST_BLOCKS)

// Per-(b,f) binary mask + handshake counters (reset at end of every launch).
__device__ __align__(16) float g_mask[B * F];
__device__ int g_done;            // mask rows published this launch (0..16)
__device__ int g_exit;            // blocks retired this launch

// kept(f) <=> #{j : x2[j] > x2[f]} < KKEEP   (tie-correct vs top_k kth value)
// binary  = kept && (x2 > 0)                 (probs > 0.5 <=> wta > 0)
__global__ void fused_kernel(const float* __restrict__ w_mask,
                             const float* __restrict__ noise,
                             const float4* __restrict__ x,
                             float4* __restrict__ out) {
    __shared__ int ready;
    const int tid = threadIdx.x;                      // 256 threads
    const int bid = blockIdx.x;

    // ---- Phase 1: blocks 0..15 publish the mask row for batch == bid ----
    if (bid < B) {
        __shared__ __align__(16) float s[F];
        const float w  = __ldg(&w_mask[tid]);
        const float sg = 1.0f / (1.0f + __expf(-w));
        const float x2 = sg + 0.05f * __ldg(&noise[bid * F + tid]);
        s[tid] = x2;
        __syncthreads();
        const float4* s4 = (const float4*)s;
        int gt = 0;
#pragma unroll 16
        for (int j = 0; j < F / 4; ++j) {             // vectorized count
            const float4 v = s4[j];                   // uniform-addr LDS.128
            gt += (v.x > x2) + (v.y > x2) + (v.z > x2) + (v.w > x2);
        }
        g_mask[bid * F + tid] = (gt < KKEEP && x2 > 0.0f) ? 1.0f : 0.0f;
        __threadfence();                              // rows visible at L2
        __syncthreads();                              // all lanes fenced
        if (tid == 0) atomicAdd(&g_done, 1);          // release
    }

    // ---- Phase 2: block-uniform flag check (tid0 reads, smem broadcast) ---
    if (tid == 0) ready = (*(volatile int*)&g_done >= B) ? 1 : 0;
    __syncthreads();                                  // uniform decision

    if (bid < MASKED_BLOCKS) {
        const int baseV = bid * BLK_F4;               // first f4 index
        const int row   = baseV >> 11;                // (b*F + f), uniform

        if (ready) {
            // Fast path (vast majority): acquire fence, then R8 skip body.
            __threadfence();                          // no stale/speculated ld
            const float m = __ldg(&g_mask[row]);
            if (m != 0.0f) {
                float4 xv[4];
#pragma unroll
                for (int k = 0; k < 4; ++k)           // front-batched (MLP=4)
                    xv[k] = __ldcs(&x[baseV + k * 256 + tid]);
#pragma unroll
                for (int k = 0; k < 4; ++k)
                    __stcs(&out[baseV + k * 256 + tid], xv[k]);
            } else {
                const float4 z = make_float4(0.f, 0.f, 0.f, 0.f);
#pragma unroll
                for (int k = 0; k < 4; ++k)           // row dropped: no reads
                    __stcs(&out[baseV + k * 256 + tid], z);
            }
        } else {
            // Wave-1 slow path: prefetch reads UNDER the mask window.
            float4 xv[4];
#pragma unroll
            for (int k = 0; k < 4; ++k)
                xv[k] = __ldcs(&x[baseV + k * 256 + tid]);
            if (tid == 0) {                           // tid0-only poll (safe)
                while (*(volatile int*)&g_done < B) __nanosleep(64);
            }
            __syncthreads();                          // all threads released
            __threadfence();                          // acquire before mask ld
            const float m = __ldg(&g_mask[row]);
#pragma unroll
            for (int k = 0; k < 4; ++k) {
                xv[k].x *= m; xv[k].y *= m; xv[k].z *= m; xv[k].w *= m;
                __stcs(&out[baseV + k * 256 + tid], xv[k]);
            }
        }
    } else {
        // ---- binary_mask block (write-only; scheduled after masked) ----
        const int w0 = (bid - MASKED_BLOCKS) * BLK_F4;
        const int b  = w0 >> 19;                      // T*F/4 f4 per batch
        const int baseV = N4_MASKED + w0;
        if (!ready) {
            if (tid == 0) {
                while (*(volatile int*)&g_done < B) __nanosleep(64);
            }
            __syncthreads();
        }
        __threadfence();                              // acquire before mask ld
        // f4 lane = (w0 + k*256 + tid) & 63 = tid & 63 (w0, 256 ≡ 0 mod 64)
        const float4 m4 =
            __ldg(&((const float4*)g_mask)[(b << 6) + (tid & 63)]);
#pragma unroll
        for (int k = 0; k < 4; ++k)
            __stcs(&out[baseV + k * 256 + tid], m4);
    }

    // ---- Phase 4: last block out resets counters for the next replay ----
    // Safe: only tid0 ever reads g_done (each passed its poll before the
    // g_exit increment), so the reset cannot strand a spinning thread.
    if (tid == 0) {
        __threadfence();
        const int n = atomicAdd(&g_exit, 1);
        if (n == (int)gridDim.x - 1) {
            g_exit = 0;
            g_done = 0;
        }
    }
}

extern "C" void kernel_launch(void* const* d_in, const int* in_sizes, int n_in,
                              void* d_out, int out_size) {
    const float* x      = (const float*)d_in[0];   // (16,1,256,8192) f32
    const float* w_mask = (const float*)d_in[1];   // (1,1,1,256)     f32
    const float* noise  = (const float*)d_in[2];   // (16,1,1,256)    f32
    float* out = (float*)d_out;

    const bool has_bcast = ((long long)out_size >= 2LL * N1);
    const int blocks = has_bcast ? GRID_TOTAL : MASKED_BLOCKS;
    fused_kernel<<<blocks, 256>>>(w_mask, noise,
                                  (const float4*)x, (float4*)out);
}

// round 17
// speedup vs baseline: 1.0414x; 1.0414x over previous
#include <cuda_runtime.h>

// Problem constants (shapes fixed by the dataset)
#define B 16
#define F 256
#define T 8192
#define KKEEP 204                 // k = int(256 * (1 - 0.2))

#define N1 (B * F * T)            // 33,554,432 floats per output tensor
#define N4_MASKED (N1 / 4)        // 8,388,608 float4 (masked_x half)

// R8-proven streamer geometry: 256 threads, ILP 4 -> 1024 f4 per block,
// contiguous [masked | bcast] layout (R12/R13: beats any interleave).
#define BLK_F4 1024
#define MASKED_BLOCKS 8192        // 8192 * 1024 f4 = N4_MASKED
#define BCAST_BLOCKS 8192
#define GRID_TOTAL (MASKED_BLOCKS + BCAST_BLOCKS)

// Per-(b,f) binary mask + handshake counters (reset at end of every launch).
__device__ __align__(16) float g_mask[B * F];
__device__ int g_done;            // mask rows published this launch (0..16)
__device__ int g_exit;            // blocks retired this launch

// Coherent, non-hoistable loads: asm volatile + "memory" clobber pins them
// after the preceding BAR/poll (the __ldg "constant for kernel lifetime"
// contract is what let R14/R16 consume pre-publication zeros).
__device__ __forceinline__ float ld_cg_f32(const float* p) {
    float v;
    asm volatile("ld.global.cg.f32 %0, [%1];" : "=f"(v) : "l"(p) : "memory");
    return v;
}
__device__ __forceinline__ float4 ld_cg_f32x4(const float4* p) {
    float4 v;
    asm volatile("ld.global.cg.v4.f32 {%0,%1,%2,%3}, [%4];"
                 : "=f"(v.x), "=f"(v.y), "=f"(v.z), "=f"(v.w)
                 : "l"(p) : "memory");
    return v;
}

// kept(f) <=> #{j : x2[j] > x2[f]} < KKEEP   (tie-correct vs top_k kth value)
// binary  = kept && (x2 > 0)                 (probs > 0.5 <=> wta > 0)
__global__ void fused_kernel(const float* __restrict__ w_mask,
                             const float* __restrict__ noise,
                             const float4* __restrict__ x,
                             float4* __restrict__ out) {
    __shared__ int ready;
    const int tid = threadIdx.x;                      // 256 threads
    const int bid = blockIdx.x;

    // ---- Phase 1: blocks 0..15 publish the mask row for batch == bid ----
    if (bid < B) {
        __shared__ __align__(16) float s[F];
        const float w  = __ldg(&w_mask[tid]);
        const float sg = 1.0f / (1.0f + __expf(-w));
        const float x2 = sg + 0.05f * __ldg(&noise[bid * F + tid]);
        s[tid] = x2;
        __syncthreads();
        const float4* s4 = (const float4*)s;
        int gt = 0;
#pragma unroll 16
        for (int j = 0; j < F / 4; ++j) {             // vectorized count
            const float4 v = s4[j];                   // uniform-addr LDS.128
            gt += (v.x > x2) + (v.y > x2) + (v.z > x2) + (v.w > x2);
        }
        g_mask[bid * F + tid] = (gt < KKEEP && x2 > 0.0f) ? 1.0f : 0.0f;
        __threadfence();                              // rows visible at L2
        __syncthreads();                              // all lanes fenced
        if (tid == 0) atomicAdd(&g_done, 1);          // release
    }

    // ---- Phase 2+3: streamer (tid0 poll + BAR; coherent mask loads) ----
    if (bid < MASKED_BLOCKS) {
        const int baseV = bid * BLK_F4;               // first f4 index
        const int row   = baseV >> 11;                // (b*F + f), uniform

        if (tid == 0) ready = (*(volatile int*)&g_done >= B) ? 1 : 0;
        __syncthreads();                              // uniform decision

        if (ready) {
            // Fast path (all blocks after the ~2us window): R8 skip body.
            const float m = ld_cg_f32(&g_mask[row]);  // pinned after BAR
            if (m != 0.0f) {
                float4 xv[4];
#pragma unroll
                for (int k = 0; k < 4; ++k)           // front-batched (MLP=4)
                    xv[k] = __ldcs(&x[baseV + k * 256 + tid]);
#pragma unroll
                for (int k = 0; k < 4; ++k)
                    __stcs(&out[baseV + k * 256 + tid], xv[k]);
            } else {
                const float4 z = make_float4(0.f, 0.f, 0.f, 0.f);
#pragma unroll
                for (int k = 0; k < 4; ++k)           // row dropped: no reads
                    __stcs(&out[baseV + k * 256 + tid], z);
            }
        } else {
            // Wave-1 slow path: spend the mask window on reads, not idling.
            float4 xv[4];
#pragma unroll
            for (int k = 0; k < 4; ++k)
                xv[k] = __ldcs(&x[baseV + k * 256 + tid]);
            if (tid == 0) {
                while (*(volatile int*)&g_done < B) __nanosleep(64);
            }
            __syncthreads();                          // release all threads
            const float m = ld_cg_f32(&g_mask[row]);  // pinned after BAR
#pragma unroll
            for (int k = 0; k < 4; ++k) {
                xv[k].x *= m; xv[k].y *= m; xv[k].z *= m; xv[k].w *= m;
                __stcs(&out[baseV + k * 256 + tid], xv[k]);
            }
        }
    } else {
        // ---- binary_mask block (write-only; scheduled after masked) ----
        const int w0 = (bid - MASKED_BLOCKS) * BLK_F4;
        const int b  = w0 >> 19;                      // T*F/4 f4 per batch
        const int baseV = N4_MASKED + w0;
        if (tid == 0) {                               // usually exits at once
            while (*(volatile int*)&g_done < B) __nanosleep(64);
        }
        __syncthreads();
        // f4 lane = (w0 + k*256 + tid) & 63 = tid & 63 (w0, 256 ≡ 0 mod 64)
        const float4 m4 =
            ld_cg_f32x4(&((const float4*)g_mask)[(b << 6) + (tid & 63)]);
#pragma unroll
        for (int k = 0; k < 4; ++k)
            __stcs(&out[baseV + k * 256 + tid], m4);
    }

    // ---- Phase 4: last block out resets counters for the next replay ----
    // Safe: a block increments g_exit only after its tid0 passed the poll,
    // so when the count completes nobody can still be reading g_done.
    if (tid == 0) {
        const int n = atomicAdd(&g_exit, 1);
        if (n == (int)gridDim.x - 1) {
            g_exit = 0;
            g_done = 0;
        }
    }
}

extern "C" void kernel_launch(void* const* d_in, const int* in_sizes, int n_in,
                              void* d_out, int out_size) {
    const float* x      = (const float*)d_in[0];   // (16,1,256,8192) f32
    const float* w_mask = (const float*)d_in[1];   // (1,1,1,256)     f32
    const float* noise  = (const float*)d_in[2];   // (16,1,1,256)    f32
    float* out = (float*)d_out;

    const bool has_bcast = ((long long)out_size >= 2LL * N1);
    const int blocks = has_bcast ? GRID_TOTAL : MASKED_BLOCKS;
    fused_kernel<<<blocks, 256>>>(w_mask, noise,
                                  (const float4*)x, (float4*)out);
}